// round 11
// baseline (speedup 1.0000x reference)
#include <cuda_runtime.h>
#include <math.h>

#define NB 16
#define NH 320
#define NW 320
#define NPIX (NB * NH * NW)
#define NWORDS 10            // 320 / 32
#define ROWS1 4              // rows per pass-1 block
#define SENTINEL 20000       // "no seed in this row" distance stand-in
#define INV_N (1.0f / (float)NPIX)

// Packed pass-1 output: short2 per pixel = (pred code, target code).
//  code > 0 : pixel is fg (mask=1); code = dist to nearest 0 in row
//  code < 0 : pixel is bg (mask=0); -code = dist to nearest 1 in row
__device__ short2 g_code2[NPIX];
__device__ int g_hasfg[2][NB];   // zero-init at load; OR is idempotent across replays

// Nearest set bit to center (bit 32) of a 64-bit window. Returns -1 if none.
__device__ __forceinline__ int ndist(unsigned long long v) {
    if (!v) return -1;
    unsigned long long t = v >> 32;
    int dR = t ? (__ffsll((long long)t) - 1) : 1000;
    unsigned long long u = v << 32;
    int dL = u ? (__clzll((long long)u) + 1) : 1000;
    return min(dR, dL);
}

// Rare fallback: nearest bit equal to want_one at distance > 32.
__device__ int far_search(const unsigned int* w, int x, int want_one) {
    for (int d = 33; d < NW; d++) {
        int l = x - d, r = x + d;
        if (l >= 0) { int b = (w[l >> 5] >> (l & 31)) & 1; if (b == want_one) return d; }
        if (r < NW) { int b = (w[r >> 5] >> (r & 31)) & 1; if (b == want_one) return d; }
    }
    return SENTINEL;
}

__device__ __forceinline__ int row_code(const unsigned int* w, int c, int o,
                                        unsigned long long validw, int bit, int x) {
    unsigned int w0 = (c > 0) ? w[c - 1] : 0u;
    unsigned int w1 = w[c];
    unsigned int w2 = (c < NWORDS - 1) ? w[c + 1] : 0u;
    unsigned long long lo = (unsigned long long)w0 | ((unsigned long long)w1 << 32);
    unsigned long long win = lo >> o;
    if (o) win |= (unsigned long long)w2 << (64 - o);
    if (bit) {                       // fg pixel: nearest 0
        int d = ndist((~win) & validw);
        if (d < 0) d = far_search(w, x, 0);
        return d;
    } else {                         // bg pixel: nearest 1
        int d = ndist(win & validw);
        if (d < 0) d = far_search(w, x, 1);
        return -d;
    }
}

// Pass 1: one block = ROWS1 rows of one image. 320 threads.
__global__ void __launch_bounds__(NW)
hd_pass1_kernel(const float* __restrict__ pred,
                const float* __restrict__ tgt,
                float* __restrict__ out) {
    const int y0 = blockIdx.x * ROWS1;
    const int n = blockIdx.y;
    const int x = threadIdx.x;

    if (blockIdx.x == 0 && n == 0 && x == 0) out[0] = 0.0f;

    __shared__ unsigned int wp[ROWS1][NWORDS];
    __shared__ unsigned int wt[ROWS1][NWORDS];

    const int base = (n * NH + y0) * NW + x;

    // Front-load all inputs: 8 independent global loads, one latency exposure.
    float pv[ROWS1], tv[ROWS1];
#pragma unroll
    for (int k = 0; k < ROWS1; k++) {
        pv[k] = pred[base + k * NW];
        tv[k] = tgt[base + k * NW];
    }

    const int lane = x & 31, wid = x >> 5;
    int bp[ROWS1], bt[ROWS1];
#pragma unroll
    for (int k = 0; k < ROWS1; k++) {
        bp[k] = (pv[k] > 0.5f) ? 1 : 0;
        bt[k] = (tv[k] > 0.5f) ? 1 : 0;
        const unsigned int balp = __ballot_sync(0xffffffffu, bp[k]);
        const unsigned int balt = __ballot_sync(0xffffffffu, bt[k]);
        if (lane == 0) { wp[k][wid] = balp; wt[k][wid] = balt; }
    }

    __syncthreads();   // publish all rows

    if (x == 0) {
        unsigned int pa = 0u, ta = 0u;
#pragma unroll
        for (int k = 0; k < ROWS1; k++)
#pragma unroll
            for (int i = 0; i < NWORDS; i++) { pa |= wp[k][i]; ta |= wt[k][i]; }
        if (pa) atomicOr(&g_hasfg[0][n], 1);
        if (ta) atomicOr(&g_hasfg[1][n], 1);
    }

    unsigned long long validw = ~0ULL;
    if (x < 32)  validw <<= (32 - x);
    if (x > 288) validw &= (~0ULL >> (x - 288));

#pragma unroll
    for (int k = 0; k < ROWS1; k++) {
        const int cP = row_code(wp[k], wid, lane, validw, bp[k], x);
        const int cT = row_code(wt[k], wid, lane, validw, bt[k], x);
        g_code2[base + k * NW] = make_short2((short)cP, (short)cT);
    }
}

// Pass 2 + fused loss. One block = one row of one image, 320 threads.
// Unrolled r=1..4 (independent loads, full MLP), rare warp-uniform tail for r>=5.
__global__ void __launch_bounds__(NW)
hd_pass2_kernel(const float* __restrict__ pred,
                const float* __restrict__ tgt,
                float* __restrict__ out) {
    const int y = blockIdx.x;
    const int n = blockIdx.y;
    const int x = threadIdx.x;

    const int plane = n * NH * NW;
    const int idx = plane + y * NW + x;

    const float pv = pred[idx];
    const float tv = tgt[idx];
    const short2 c0 = g_code2[idx];

    const int cp = c0.x, ct = c0.y;
    const int sP = (cp > 0) ? 1 : -1;
    const int sT = (ct > 0) ? 1 : -1;
    const int aP = abs(cp), aT = abs(ct);
    int bestP = aP * aP;
    int bestT = aT * aT;
    int bmax = max(bestP, bestT);

    const int rUp = y;            // up neighbor valid while r <= y
    const int rDn = NH - 1 - y;   // down neighbor valid while r <= NH-1-y
    const short2* colbase = g_code2 + plane + x;

    if (__any_sync(0xffffffffu, bmax > 1)) {
        // Phase 1: fixed r = 1..4, no inter-iteration dependence -> 8 parallel loads.
#pragma unroll
        for (int r = 1; r <= 4; r++) {
            if (r <= rUp) {
                const short2 v = colbase[(y - r) * NW];
                const int dP = max(sP * (int)v.x, 0);
                const int dT = max(sT * (int)v.y, 0);
                bestP = min(bestP, dP * dP + r * r);
                bestT = min(bestT, dT * dT + r * r);
            }
            if (r <= rDn) {
                const short2 v = colbase[(y + r) * NW];
                const int dP = max(sP * (int)v.x, 0);
                const int dT = max(sT * (int)v.y, 0);
                bestP = min(bestP, dP * dP + r * r);
                bestT = min(bestT, dT * dT + r * r);
            }
        }
        bmax = max(bestP, bestT);

        // Phase 2 (rare): warp-uniform tail for r >= 5.
        int r = 5, r2 = 25;
        while (__any_sync(0xffffffffu, r2 < bmax)) {
            if (r <= rUp) {
                const short2 v = colbase[(y - r) * NW];
                const int dP = max(sP * (int)v.x, 0);
                const int dT = max(sT * (int)v.y, 0);
                bestP = min(bestP, dP * dP + r2);
                bestT = min(bestT, dT * dT + r2);
            }
            if (r <= rDn) {
                const short2 v = colbase[(y + r) * NW];
                const int dP = max(sP * (int)v.x, 0);
                const int dT = max(sT * (int)v.y, 0);
                bestP = min(bestP, dP * dP + r2);
                bestT = min(bestT, dT * dT + r2);
            }
            bmax = max(bestP, bestT);
            r += 1;
            r2 += (r << 1) - 1;           // r2 = r*r incrementally
        }
    }

    // dt^2 = active-field squared EDT (complementary field is 0 at every pixel)
    const float dt2p = g_hasfg[0][n] ? (float)bestP : 0.0f;
    const float dt2t = g_hasfg[1][n] ? (float)bestT : 0.0f;

    const float e = pv - tv;
    float v = e * e * (dt2p + dt2t) * INV_N;

#pragma unroll
    for (int off = 16; off > 0; off >>= 1)
        v += __shfl_down_sync(0xffffffffu, v, off);

    __shared__ float wsum[NW / 32];
    const int lane = x & 31;
    const int wid = x >> 5;
    if (lane == 0) wsum[wid] = v;
    __syncthreads();
    if (x == 0) {
        float s = 0.0f;
#pragma unroll
        for (int i = 0; i < NW / 32; i++) s += wsum[i];
        atomicAdd(out, s);
    }
}

extern "C" void kernel_launch(void* const* d_in, const int* in_sizes, int n_in,
                              void* d_out, int out_size) {
    const float* pred = (const float*)d_in[0];
    const float* tgt  = (const float*)d_in[1];
    float* out = (float*)d_out;

    dim3 grid1(NH / ROWS1, NB);
    hd_pass1_kernel<<<grid1, NW>>>(pred, tgt, out);
    dim3 grid2(NH, NB);
    hd_pass2_kernel<<<grid2, NW>>>(pred, tgt, out);
}